// round 5
// baseline (speedup 1.0000x reference)
#include <cuda_runtime.h>
#include <cuda_bf16.h>
#include <math.h>

#define Bz 16
#define Sz 256
#define Cz 17
#define Nz 16
#define Dz 32
#define Ez 4
#define Hz 4
#define DHz 8
#define DFFz 64
#define FULLM 0xffffffffu

// ---------------- scratch (static device memory; no allocations) -------------
__device__ float g_xns[Bz * Sz * Nz];
__device__ float g_q[Bz * Nz * Sz * Dz];
__device__ float g_k[Bz * Nz * Sz * Dz];
__device__ float g_v[Bz * Nz * Sz * Dz];
__device__ int   g_assign[Bz * Sz];
__device__ int   g_lists[Bz * Ez * Sz];
__device__ int   g_counts[Bz * Ez];
__device__ float g_k0[Ez * Dz];
__device__ float g_v0[Ez * Dz];

// ---------------- kernel A: trend + Fourier season + new_x -------------------
// one block per (b, channel c<N); 256 threads (t = time index)
__global__ void preprocess_kernel(const float* __restrict__ x) {
    int blk = blockIdx.x;
    int b = blk / Nz;
    int c = blk % Nz;
    int t = threadIdx.x;

    __shared__ float xs[Sz];
    __shared__ float ctab[Sz], stab[Sz];
    __shared__ float re_s[129], im_s[129], amp_s[129], amp2_s[129];
    __shared__ float keptre[32], keptim[32];
    __shared__ int   keptf[32];
    __shared__ int   nkept_s;
    __shared__ float thr_s;

    if (t == 0) nkept_s = 0;
    xs[t] = x[(b * Sz + t) * Cz + c];
    float ang = (float)t / 128.0f;           // 2*pi*t/256 in "pi units"
    ctab[t] = cospif(ang);
    stab[t] = sinpif(ang);
    __syncthreads();

    // direct real DFT: X[f] = sum_t x[t] * exp(-2*pi*i*f*t/256)
    if (t < 129) {
        float re = 0.f, im = 0.f;
        for (int u = 0; u < Sz; u++) {
            int idx = (t * u) & 255;
            float xv = xs[u];
            re += xv * ctab[idx];
            im -= xv * stab[idx];
        }
        re_s[t] = re;
        im_s[t] = im;
        float a = (t == 0) ? -1e38f : sqrtf(re * re + im * im);  // amp[0] = -inf
        amp_s[t] = a;
        amp2_s[t] = a;
    }
    __syncthreads();

    // warp 0: 4th-largest amplitude via 4 parallel argmax passes (packed u64)
    if (t < 32) {
        float thr = 0.f;
        for (int pass = 0; pass < 4; pass++) {
            unsigned long long best = 0ull;
            #pragma unroll
            for (int cc = 0; cc < 5; cc++) {
                int f = cc * 32 + t;
                if (f < 129) {
                    float a = amp2_s[f];
                    if (a > -1e37f) {
                        unsigned long long u =
                            (((unsigned long long)__float_as_uint(a)) << 32) |
                            (unsigned)f;
                        if (u > best) best = u;
                    }
                }
            }
            #pragma unroll
            for (int off = 16; off > 0; off >>= 1) {
                unsigned long long o2 = __shfl_xor_sync(FULLM, best, off);
                if (o2 > best) best = o2;
            }
            int bi = (int)(best & 0xffffffffu);
            thr = __uint_as_float((unsigned)(best >> 32));
            if (t == 0) amp2_s[bi] = -1e38f;
            __syncwarp();
        }
        if (t == 0) thr_s = thr;
    }
    __syncthreads();

    // compact kept bins on ORIGINAL amps (amp >= thresh); order irrelevant
    float thr = thr_s;
    if (t < 129 && amp_s[t] >= thr) {
        int p = atomicAdd(&nkept_s, 1);
        if (p < 32) {
            keptf[p] = t;
            keptre[p] = re_s[t];
            keptim[p] = im_s[t];
        }
    }
    __syncthreads();

    // season[t] = irfft of masked spectrum (only kept bins)
    float season = 0.f;
    int nk = min(nkept_s, 32);
    for (int j = 0; j < nk; j++) {
        int f = keptf[j];
        float cr = keptre[j], ci = keptim[j];
        int idx = (f * t) & 255;
        if (f == 0)        season += cr;
        else if (f == 128) season += cr * ctab[idx];
        else               season += 2.f * (cr * ctab[idx] - ci * stab[idx]);
    }
    season *= (1.0f / 256.0f);

    // trend: average of moving averages k=4,8,12 (edge-replicated == clamped)
    float s4 = 0.f, s8 = 0.f, s12 = 0.f;
    #pragma unroll
    for (int i = -1; i <= 2; i++) { int u = min(max(t + i, 0), Sz - 1); s4 += xs[u]; }
    #pragma unroll
    for (int i = -3; i <= 4; i++) { int u = min(max(t + i, 0), Sz - 1); s8 += xs[u]; }
    #pragma unroll
    for (int i = -5; i <= 6; i++) { int u = min(max(t + i, 0), Sz - 1); s12 += xs[u]; }
    float trend = (s4 * 0.25f + s8 * 0.125f + s12 * (1.0f / 12.0f)) * (1.0f / 3.0f);

    g_xns[(b * Sz + t) * Nz + c] = xs[t] + season + trend;
}

// ---------------- kernel B: routing + lists + background k0/v0 ---------------
__global__ void assign_kernel(const float* __restrict__ ox,
                              const float* __restrict__ start_b,
                              const float* __restrict__ ln1_g,
                              const float* __restrict__ ln1_b,
                              const float* __restrict__ Wk,
                              const float* __restrict__ Wv) {
    int t = threadIdx.x;
    __shared__ float red[256];
    __shared__ float smin_s, smax_s;

    float mn = 3.4e38f, mx = -3.4e38f;
    for (int i = t; i < Bz * Sz; i += 256) {
        float s = ox[i * 2 + 1];
        mn = fminf(mn, s);
        mx = fmaxf(mx, s);
    }
    red[t] = mn; __syncthreads();
    for (int o = 128; o > 0; o >>= 1) {
        if (t < o) red[t] = fminf(red[t], red[t + o]);
        __syncthreads();
    }
    if (t == 0) smin_s = red[0];
    __syncthreads();
    red[t] = mx; __syncthreads();
    for (int o = 128; o > 0; o >>= 1) {
        if (t < o) red[t] = fmaxf(red[t], red[t + o]);
        __syncthreads();
    }
    if (t == 0) smax_s = red[0];
    __syncthreads();

    float bmin = smin_s, bmax = smax_s;
    float step = (bmax - bmin) * 0.25f;
    for (int i = t; i < Bz * Sz; i += 256) {
        float s = ox[i * 2 + 1];
        int cntb = 0;
        #pragma unroll
        for (int k = 0; k < 5; k++) {
            float bv = bmin + step * (float)k;
            if (bv <= s) cntb++;
        }
        int a = cntb - 1;
        a = max(0, min(Ez - 1, a));
        g_assign[i] = a;
    }
    __syncthreads();

    // per-(b,e) ascending token lists via warp ballot compaction
    int warp = t >> 5, lane = t & 31;
    for (int pe = warp; pe < Bz * Ez; pe += 8) {
        int b = pe / Ez, e = pe % Ez;
        int cnt = 0;
        for (int s0 = 0; s0 < Sz; s0 += 32) {
            int s = s0 + lane;
            int a = g_assign[b * Sz + s];
            unsigned bal = __ballot_sync(FULLM, a == e);
            int pos = cnt + __popc(bal & ((1u << lane) - 1u));
            if (a == e) g_lists[pe * Sz + pos] = s;
            cnt += __popc(bal);
        }
        if (lane == 0) g_counts[pe] = cnt;
    }

    // background key/value: unassigned tokens have hidden = start_b (const)
    if (t < Ez * Dz) {
        int e = t / Dz, d = t % Dz;
        float m = 0.f;
        for (int i = 0; i < Dz; i++) m += start_b[i];
        m *= (1.0f / Dz);
        float var = 0.f;
        for (int i = 0; i < Dz; i++) { float dd = start_b[i] - m; var += dd * dd; }
        var *= (1.0f / Dz);
        float rs = rsqrtf(var + 1e-5f);
        float k0 = 0.f, v0 = 0.f;
        for (int i = 0; i < Dz; i++) {
            float z = (start_b[i] - m) * rs * ln1_g[e * Dz + i] + ln1_b[e * Dz + i];
            k0 += z * Wk[(e * Dz + i) * Dz + d];
            v0 += z * Wv[(e * Dz + i) * Dz + d];
        }
        g_k0[e * Dz + d] = k0;
        g_v0[e * Dz + d] = v0;
    }
}

// ---------------- kernel C: expert-grouped LN1 + Q/K/V projections -----------
// one block per (b,e,tile); 128 threads; weights staged once per block
__global__ __launch_bounds__(128) void qkv_kernel(const float* __restrict__ sW,
                                                  const float* __restrict__ sb,
                                                  const float* __restrict__ Wq,
                                                  const float* __restrict__ Wk,
                                                  const float* __restrict__ Wv,
                                                  const float* __restrict__ ln1_g,
                                                  const float* __restrict__ ln1_b) {
    int blk = blockIdx.x;
    int pe = blk >> 3, tile = blk & 7;
    int b = pe / Ez, e = pe % Ez;
    int cnt = g_counts[pe];
    int t = threadIdx.x;

    __shared__ float Ws[3][Dz * Dz];
    __shared__ float zs[Nz][Dz];
    __shared__ float g1s[Dz], bl1s[Dz], sWs[Dz], sbs[Dz];

    for (int i = t; i < Dz * Dz; i += 128) {
        Ws[0][i] = Wq[e * Dz * Dz + i];
        Ws[1][i] = Wk[e * Dz * Dz + i];
        Ws[2][i] = Wv[e * Dz * Dz + i];
    }
    if (t < Dz) {
        g1s[t] = ln1_g[e * Dz + t];
        bl1s[t] = ln1_b[e * Dz + t];
        sWs[t] = sW[t];
        sbs[t] = sb[t];
    }
    __syncthreads();

    const int* lst = &g_lists[pe * Sz];
    for (int ti = tile; ti < cnt; ti += 8) {
        int s = lst[ti];
        if (t < Nz) {
            float a = g_xns[(b * Sz + s) * Nz + t];
            float h[Dz];
            float m = 0.f;
            #pragma unroll
            for (int i = 0; i < Dz; i++) { h[i] = a * sWs[i] + sbs[i]; m += h[i]; }
            m *= (1.0f / Dz);
            float var = 0.f;
            #pragma unroll
            for (int i = 0; i < Dz; i++) { float d = h[i] - m; var += d * d; }
            var *= (1.0f / Dz);
            float rs = rsqrtf(var + 1e-5f);
            #pragma unroll
            for (int i = 0; i < Dz; i++)
                zs[t][i] = (h[i] - m) * rs * g1s[i] + bl1s[i];
        }
        __syncthreads();

        for (int o = t; o < 3 * Nz * Dz; o += 128) {
            int mat = o >> 9;
            int r = o & 511;
            int n = r >> 5, d = r & 31;
            const float* W = Ws[mat];
            float acc = 0.f;
            #pragma unroll
            for (int i = 0; i < Dz; i++) acc += zs[n][i] * W[i * Dz + d];
            float* dst = (mat == 0) ? g_q : ((mat == 1) ? g_k : g_v);
            dst[((b * Nz + n) * Sz + s) * Dz + d] = acc;
        }
        __syncthreads();
    }
}

// ---------------- kernel D: FUSED attention + Wo + LN2 + FFN -----------------
// grid = (b,e) * 8 parts; block 128 (4 warps); lane = query; block owns 2
// channels; single-pass softmax referenced to the background logit l0.
// Register discipline: no att[] array (inv folded into Wo pass), FFN f in
// 8-wide chunks; cap 3 blocks/SM (~170 regs) so nothing spills.
__global__ __launch_bounds__(128, 3) void attn_tail_kernel(
        const float* __restrict__ sW,  const float* __restrict__ sb,
        const float* __restrict__ Wo,  const float* __restrict__ ln2_g,
        const float* __restrict__ ln2_b,
        const float* __restrict__ W1,  const float* __restrict__ b1,
        const float* __restrict__ W2,  const float* __restrict__ b2,
        float* __restrict__ out) {
    int blk = blockIdx.x;
    int part = blk & 7;
    int pe = blk >> 3;
    int b = pe / Ez, e = pe % Ez;
    int cnt = g_counts[pe];
    if (cnt == 0) return;

    int t = threadIdx.x, warp = t >> 5, lane = t & 31;

    __shared__ float Wos[Dz * Dz];       // 4KB
    __shared__ float W1s[Dz * DFFz];     // 8KB
    __shared__ float W2s[DFFz * Dz];     // 8KB
    __shared__ float k0s[Dz], v0s[Dz], sWs[Dz], sbs[Dz];
    __shared__ float g2s[Dz], bl2s[Dz], b1ss[DFFz], b2ss[Dz];
    __shared__ int lst_s[Sz];

    for (int i = t; i < Dz * Dz; i += 128)  Wos[i] = Wo[e * Dz * Dz + i];
    for (int i = t; i < Dz * DFFz; i += 128) W1s[i] = W1[e * Dz * DFFz + i];
    for (int i = t; i < DFFz * Dz; i += 128) W2s[i] = W2[e * DFFz * Dz + i];
    if (t < Dz) {
        k0s[t] = g_k0[e * Dz + t];
        v0s[t] = g_v0[e * Dz + t];
        sWs[t] = sW[t];
        sbs[t] = sb[t];
        g2s[t] = ln2_g[e * Dz + t];
        bl2s[t] = ln2_b[e * Dz + t];
        b2ss[t] = b2[e * Dz + t];
    }
    if (t < DFFz) b1ss[t] = b1[e * DFFz + t];
    for (int i = t; i < cnt; i += 128) lst_s[i] = g_lists[pe * Sz + i];
    __syncthreads();

    int nchunk = (cnt + 31) >> 5;
    int items = 2 * nchunk;              // 2 channels per block
    int n0 = part * 2;
    const float scale = 0.35355339059327373f;   // 1/sqrt(8)
    float fnbg = (float)(Sz - cnt);

    for (int it = warp; it < items; it += 4) {
        int n = n0 + it / nchunk;
        int ck = it % nchunk;
        int qi = ck * 32 + lane;
        bool active = qi < cnt;
        int sq = lst_s[active ? qi : (cnt - 1)];
        long nb = (long)(b * Nz + n) * Sz;

        // ---- load this lane's query ----
        float qv[Dz];
        {
            const float4* qg = (const float4*)(g_q + (nb + sq) * Dz);
            #pragma unroll
            for (int f = 0; f < 8; f++) {
                float4 v = __ldg(qg + f);
                qv[f * 4 + 0] = v.x; qv[f * 4 + 1] = v.y;
                qv[f * 4 + 2] = v.z; qv[f * 4 + 3] = v.w;
            }
        }

        // ---- background logit as exp reference; init accumulators ----
        float l0[Hz], den[Hz], o[Hz][DHz];
        #pragma unroll
        for (int h = 0; h < Hz; h++) {
            float l = 0.f;
            #pragma unroll
            for (int i = 0; i < DHz; i++) l += qv[h * 8 + i] * k0s[h * 8 + i];
            l0[h] = l * scale;
            den[h] = fnbg;                    // nbg * exp(l0 - l0)
            #pragma unroll
            for (int i = 0; i < DHz; i++) o[h][i] = fnbg * v0s[h * 8 + i];
        }

        // ---- single pass over this expert's keys ----
        const float4* kb = (const float4*)(g_k + nb * Dz);
        const float4* vb = (const float4*)(g_v + nb * Dz);
        for (int j = 0; j < cnt; j++) {
            int sj = lst_s[j];
            const float4* kr = kb + sj * 8;
            const float4* vr = vb + sj * 8;
            #pragma unroll
            for (int h = 0; h < Hz; h++) {
                float4 a = __ldg(kr + h * 2), cc = __ldg(kr + h * 2 + 1);
                float l = qv[h*8+0]*a.x + qv[h*8+1]*a.y + qv[h*8+2]*a.z + qv[h*8+3]*a.w
                        + qv[h*8+4]*cc.x + qv[h*8+5]*cc.y + qv[h*8+6]*cc.z + qv[h*8+7]*cc.w;
                float w = __expf(l * scale - l0[h]);
                den[h] += w;
                float4 va = __ldg(vr + h * 2), vc = __ldg(vr + h * 2 + 1);
                o[h][0] += w * va.x; o[h][1] += w * va.y;
                o[h][2] += w * va.z; o[h][3] += w * va.w;
                o[h][4] += w * vc.x; o[h][5] += w * vc.y;
                o[h][6] += w * vc.z; o[h][7] += w * vc.w;
            }
        }

        // ---- fused tail: start h1, fold (o*inv) @ Wo directly (no att[]) ----
        float xsv = __ldg(&g_xns[(b * Sz + sq) * Nz + n]);
        float h1[Dz];
        #pragma unroll
        for (int i = 0; i < Dz; i++) h1[i] = xsv * sWs[i] + sbs[i];
        #pragma unroll
        for (int h = 0; h < Hz; h++) {
            float inv = 1.0f / den[h];
            #pragma unroll
            for (int jh = 0; jh < DHz; jh++) {
                float aj = o[h][jh] * inv;
                int j = h * DHz + jh;
                #pragma unroll
                for (int i = 0; i < Dz; i++) h1[i] += aj * Wos[j * Dz + i];
            }
        }

        // LN2 (lane-local)
        float mu = 0.f;
        #pragma unroll
        for (int i = 0; i < Dz; i++) mu += h1[i];
        mu *= (1.0f / Dz);
        float var = 0.f;
        #pragma unroll
        for (int i = 0; i < Dz; i++) { float d = h1[i] - mu; var += d * d; }
        var *= (1.0f / Dz);
        float rs = rsqrtf(var + 1e-5f);
        float z2[Dz];
        #pragma unroll
        for (int i = 0; i < Dz; i++)
            z2[i] = (h1[i] - mu) * rs * g2s[i] + bl2s[i];
        #pragma unroll
        for (int i = 0; i < Dz; i++) h1[i] += b2ss[i];

        // FFN in 8-wide f chunks: f = relu(z2@W1+b1); h1 += f@W2
        #pragma unroll
        for (int cch = 0; cch < DFFz / 8; cch++) {
            float f[8];
            #pragma unroll
            for (int j = 0; j < 8; j++) f[j] = b1ss[cch * 8 + j];
            #pragma unroll
            for (int i = 0; i < Dz; i++) {
                float zi = z2[i];
                #pragma unroll
                for (int j = 0; j < 8; j++)
                    f[j] += zi * W1s[i * DFFz + cch * 8 + j];
            }
            #pragma unroll
            for (int j = 0; j < 8; j++) {
                float fv = fmaxf(f[j], 0.f);
                #pragma unroll
                for (int i = 0; i < Dz; i++)
                    h1[i] += fv * W2s[(cch * 8 + j) * Dz + i];
            }
        }

        if (active) {
            float4* dst = (float4*)(out + ((long)(b * Sz + sq) * Nz + n) * Dz);
            #pragma unroll
            for (int f4 = 0; f4 < 8; f4++)
                dst[f4] = make_float4(h1[f4 * 4 + 0], h1[f4 * 4 + 1],
                                      h1[f4 * 4 + 2], h1[f4 * 4 + 3]);
        }
    }
}

// ---------------- launch ------------------------------------------------------
extern "C" void kernel_launch(void* const* d_in, const int* in_sizes, int n_in,
                              void* d_out, int out_size) {
    const float* x        = (const float*)d_in[0];
    const float* ox       = (const float*)d_in[1];
    const float* start_W  = (const float*)d_in[2];
    const float* start_b  = (const float*)d_in[3];
    const float* Wq       = (const float*)d_in[4];
    const float* Wk       = (const float*)d_in[5];
    const float* Wv       = (const float*)d_in[6];
    const float* Wo       = (const float*)d_in[7];
    const float* ln1_g    = (const float*)d_in[8];
    const float* ln1_b    = (const float*)d_in[9];
    const float* ln2_g    = (const float*)d_in[10];
    const float* ln2_b    = (const float*)d_in[11];
    const float* W1       = (const float*)d_in[12];
    const float* b1       = (const float*)d_in[13];
    const float* W2       = (const float*)d_in[14];
    const float* b2       = (const float*)d_in[15];
    float* out = (float*)d_out;

    preprocess_kernel<<<Bz * Nz, 256>>>(x);
    assign_kernel<<<1, 256>>>(ox, start_b, ln1_g, ln1_b, Wk, Wv);
    qkv_kernel<<<Bz * Ez * 8, 128>>>(start_W, start_b, Wq, Wk, Wv, ln1_g, ln1_b);
    attn_tail_kernel<<<Bz * Ez * 8, 128>>>(start_W, start_b, Wo, ln2_g, ln2_b,
                                           W1, b1, W2, b2, out);
}

// round 6
// speedup vs baseline: 1.1625x; 1.1625x over previous
#include <cuda_runtime.h>
#include <cuda_bf16.h>
#include <math.h>

#define Bz 16
#define Sz 256
#define Cz 17
#define Nz 16
#define Dz 32
#define Ez 4
#define Hz 4
#define DHz 8
#define DFFz 64
#define FULLM 0xffffffffu

// ---------------- scratch (static device memory; no allocations) -------------
__device__ float g_xns[Bz * Sz * Nz];
__device__ float g_q[Bz * Nz * Sz * Dz];
__device__ float g_k[Bz * Nz * Sz * Dz];
__device__ float g_v[Bz * Nz * Sz * Dz];
__device__ float g_attn[Bz * Sz * Nz * Dz];        // [b][s][n][d]
__device__ int   g_assign[Bz * Sz];
__device__ int   g_lists[Bz * Ez * Sz];
__device__ int   g_counts[Bz * Ez];
__device__ float g_k0[Ez * Dz];
__device__ float g_v0[Ez * Dz];

// ---------------- kernel A: trend + Fourier season + new_x -------------------
__global__ void preprocess_kernel(const float* __restrict__ x) {
    int blk = blockIdx.x;
    int b = blk / Nz;
    int c = blk % Nz;
    int t = threadIdx.x;

    __shared__ float xs[Sz];
    __shared__ float ctab[Sz], stab[Sz];
    __shared__ float re_s[129], im_s[129], amp_s[129], amp2_s[129];
    __shared__ float keptre[32], keptim[32];
    __shared__ int   keptf[32];
    __shared__ int   nkept_s;
    __shared__ float thr_s;

    if (t == 0) nkept_s = 0;
    xs[t] = x[(b * Sz + t) * Cz + c];
    float ang = (float)t / 128.0f;
    ctab[t] = cospif(ang);
    stab[t] = sinpif(ang);
    __syncthreads();

    if (t < 129) {
        float re = 0.f, im = 0.f;
        for (int u = 0; u < Sz; u++) {
            int idx = (t * u) & 255;
            float xv = xs[u];
            re += xv * ctab[idx];
            im -= xv * stab[idx];
        }
        re_s[t] = re;
        im_s[t] = im;
        float a = (t == 0) ? -1e38f : sqrtf(re * re + im * im);
        amp_s[t] = a;
        amp2_s[t] = a;
    }
    __syncthreads();

    if (t < 32) {
        float thr = 0.f;
        for (int pass = 0; pass < 4; pass++) {
            unsigned long long best = 0ull;
            #pragma unroll
            for (int cc = 0; cc < 5; cc++) {
                int f = cc * 32 + t;
                if (f < 129) {
                    float a = amp2_s[f];
                    if (a > -1e37f) {
                        unsigned long long u =
                            (((unsigned long long)__float_as_uint(a)) << 32) |
                            (unsigned)f;
                        if (u > best) best = u;
                    }
                }
            }
            #pragma unroll
            for (int off = 16; off > 0; off >>= 1) {
                unsigned long long o2 = __shfl_xor_sync(FULLM, best, off);
                if (o2 > best) best = o2;
            }
            int bi = (int)(best & 0xffffffffu);
            thr = __uint_as_float((unsigned)(best >> 32));
            if (t == 0) amp2_s[bi] = -1e38f;
            __syncwarp();
        }
        if (t == 0) thr_s = thr;
    }
    __syncthreads();

    float thr = thr_s;
    if (t < 129 && amp_s[t] >= thr) {
        int p = atomicAdd(&nkept_s, 1);
        if (p < 32) {
            keptf[p] = t;
            keptre[p] = re_s[t];
            keptim[p] = im_s[t];
        }
    }
    __syncthreads();

    float season = 0.f;
    int nk = min(nkept_s, 32);
    for (int j = 0; j < nk; j++) {
        int f = keptf[j];
        float cr = keptre[j], ci = keptim[j];
        int idx = (f * t) & 255;
        if (f == 0)        season += cr;
        else if (f == 128) season += cr * ctab[idx];
        else               season += 2.f * (cr * ctab[idx] - ci * stab[idx]);
    }
    season *= (1.0f / 256.0f);

    float s4 = 0.f, s8 = 0.f, s12 = 0.f;
    #pragma unroll
    for (int i = -1; i <= 2; i++) { int u = min(max(t + i, 0), Sz - 1); s4 += xs[u]; }
    #pragma unroll
    for (int i = -3; i <= 4; i++) { int u = min(max(t + i, 0), Sz - 1); s8 += xs[u]; }
    #pragma unroll
    for (int i = -5; i <= 6; i++) { int u = min(max(t + i, 0), Sz - 1); s12 += xs[u]; }
    float trend = (s4 * 0.25f + s8 * 0.125f + s12 * (1.0f / 12.0f)) * (1.0f / 3.0f);

    g_xns[(b * Sz + t) * Nz + c] = xs[t] + season + trend;
}

// ---------------- kernel B: routing + lists + background k0/v0 ---------------
__global__ void assign_kernel(const float* __restrict__ ox,
                              const float* __restrict__ start_b,
                              const float* __restrict__ ln1_g,
                              const float* __restrict__ ln1_b,
                              const float* __restrict__ Wk,
                              const float* __restrict__ Wv) {
    int t = threadIdx.x;
    __shared__ float red[256];
    __shared__ float smin_s, smax_s;

    float mn = 3.4e38f, mx = -3.4e38f;
    for (int i = t; i < Bz * Sz; i += 256) {
        float s = ox[i * 2 + 1];
        mn = fminf(mn, s);
        mx = fmaxf(mx, s);
    }
    red[t] = mn; __syncthreads();
    for (int o = 128; o > 0; o >>= 1) {
        if (t < o) red[t] = fminf(red[t], red[t + o]);
        __syncthreads();
    }
    if (t == 0) smin_s = red[0];
    __syncthreads();
    red[t] = mx; __syncthreads();
    for (int o = 128; o > 0; o >>= 1) {
        if (t < o) red[t] = fmaxf(red[t], red[t + o]);
        __syncthreads();
    }
    if (t == 0) smax_s = red[0];
    __syncthreads();

    float bmin = smin_s, bmax = smax_s;
    float step = (bmax - bmin) * 0.25f;
    for (int i = t; i < Bz * Sz; i += 256) {
        float s = ox[i * 2 + 1];
        int cntb = 0;
        #pragma unroll
        for (int k = 0; k < 5; k++) {
            float bv = bmin + step * (float)k;
            if (bv <= s) cntb++;
        }
        int a = cntb - 1;
        a = max(0, min(Ez - 1, a));
        g_assign[i] = a;
    }
    __syncthreads();

    int warp = t >> 5, lane = t & 31;
    for (int pe = warp; pe < Bz * Ez; pe += 8) {
        int b = pe / Ez, e = pe % Ez;
        int cnt = 0;
        for (int s0 = 0; s0 < Sz; s0 += 32) {
            int s = s0 + lane;
            int a = g_assign[b * Sz + s];
            unsigned bal = __ballot_sync(FULLM, a == e);
            int pos = cnt + __popc(bal & ((1u << lane) - 1u));
            if (a == e) g_lists[pe * Sz + pos] = s;
            cnt += __popc(bal);
        }
        if (lane == 0) g_counts[pe] = cnt;
    }

    if (t < Ez * Dz) {
        int e = t / Dz, d = t % Dz;
        float m = 0.f;
        for (int i = 0; i < Dz; i++) m += start_b[i];
        m *= (1.0f / Dz);
        float var = 0.f;
        for (int i = 0; i < Dz; i++) { float dd = start_b[i] - m; var += dd * dd; }
        var *= (1.0f / Dz);
        float rs = rsqrtf(var + 1e-5f);
        float k0 = 0.f, v0 = 0.f;
        for (int i = 0; i < Dz; i++) {
            float z = (start_b[i] - m) * rs * ln1_g[e * Dz + i] + ln1_b[e * Dz + i];
            k0 += z * Wk[(e * Dz + i) * Dz + d];
            v0 += z * Wv[(e * Dz + i) * Dz + d];
        }
        g_k0[e * Dz + d] = k0;
        g_v0[e * Dz + d] = v0;
    }
}

// ---------------- kernel C: expert-grouped LN1 + Q/K/V projections -----------
__global__ __launch_bounds__(128) void qkv_kernel(const float* __restrict__ sW,
                                                  const float* __restrict__ sb,
                                                  const float* __restrict__ Wq,
                                                  const float* __restrict__ Wk,
                                                  const float* __restrict__ Wv,
                                                  const float* __restrict__ ln1_g,
                                                  const float* __restrict__ ln1_b) {
    int blk = blockIdx.x;
    int pe = blk >> 3, tile = blk & 7;
    int b = pe / Ez, e = pe % Ez;
    int cnt = g_counts[pe];
    int t = threadIdx.x;

    __shared__ float Ws[3][Dz * Dz];
    __shared__ float zs[Nz][Dz];
    __shared__ float g1s[Dz], bl1s[Dz], sWs[Dz], sbs[Dz];

    for (int i = t; i < Dz * Dz; i += 128) {
        Ws[0][i] = Wq[e * Dz * Dz + i];
        Ws[1][i] = Wk[e * Dz * Dz + i];
        Ws[2][i] = Wv[e * Dz * Dz + i];
    }
    if (t < Dz) {
        g1s[t] = ln1_g[e * Dz + t];
        bl1s[t] = ln1_b[e * Dz + t];
        sWs[t] = sW[t];
        sbs[t] = sb[t];
    }
    __syncthreads();

    const int* lst = &g_lists[pe * Sz];
    for (int ti = tile; ti < cnt; ti += 8) {
        int s = lst[ti];
        if (t < Nz) {
            float a = g_xns[(b * Sz + s) * Nz + t];
            float h[Dz];
            float m = 0.f;
            #pragma unroll
            for (int i = 0; i < Dz; i++) { h[i] = a * sWs[i] + sbs[i]; m += h[i]; }
            m *= (1.0f / Dz);
            float var = 0.f;
            #pragma unroll
            for (int i = 0; i < Dz; i++) { float d = h[i] - m; var += d * d; }
            var *= (1.0f / Dz);
            float rs = rsqrtf(var + 1e-5f);
            #pragma unroll
            for (int i = 0; i < Dz; i++)
                zs[t][i] = (h[i] - m) * rs * g1s[i] + bl1s[i];
        }
        __syncthreads();

        for (int o = t; o < 3 * Nz * Dz; o += 128) {
            int mat = o >> 9;
            int r = o & 511;
            int n = r >> 5, d = r & 31;
            const float* W = Ws[mat];
            float acc = 0.f;
            #pragma unroll
            for (int i = 0; i < Dz; i++) acc += zs[n][i] * W[i * Dz + d];
            float* dst = (mat == 0) ? g_q : ((mat == 1) ? g_k : g_v);
            dst[((b * Nz + n) * Sz + s) * Dz + d] = acc;
        }
        __syncthreads();
    }
}

// ---------------- kernel D: attention only (lane = query) --------------------
// grid = (b,e)*8 parts; block 128 (4 warps); block owns 2 channels; flattened
// (channel, query-chunk) items across warps; single-pass softmax vs l0.
__global__ __launch_bounds__(128, 4) void attn_kernel() {
    int blk = blockIdx.x;
    int part = blk & 7;
    int pe = blk >> 3;
    int b = pe / Ez, e = pe % Ez;
    int cnt = g_counts[pe];
    if (cnt == 0) return;

    int t = threadIdx.x, warp = t >> 5, lane = t & 31;

    __shared__ float k0s[Dz], v0s[Dz];
    __shared__ int lst_s[Sz];

    if (t < Dz) {
        k0s[t] = g_k0[e * Dz + t];
        v0s[t] = g_v0[e * Dz + t];
    }
    for (int i = t; i < cnt; i += 128) lst_s[i] = g_lists[pe * Sz + i];
    __syncthreads();

    int nchunk = (cnt + 31) >> 5;
    int items = 2 * nchunk;
    int n0 = part * 2;
    const float scale = 0.35355339059327373f;   // 1/sqrt(8)
    float fnbg = (float)(Sz - cnt);

    for (int it = warp; it < items; it += 4) {
        int n = n0 + it / nchunk;
        int ck = it % nchunk;
        int qi = ck * 32 + lane;
        bool active = qi < cnt;
        int sq = lst_s[active ? qi : (cnt - 1)];
        long nb = (long)(b * Nz + n) * Sz;

        float qv[Dz];
        {
            const float4* qg = (const float4*)(g_q + (nb + sq) * Dz);
            #pragma unroll
            for (int f = 0; f < 8; f++) {
                float4 v = __ldg(qg + f);
                qv[f * 4 + 0] = v.x; qv[f * 4 + 1] = v.y;
                qv[f * 4 + 2] = v.z; qv[f * 4 + 3] = v.w;
            }
        }

        float l0[Hz], den[Hz], o[Hz][DHz];
        #pragma unroll
        for (int h = 0; h < Hz; h++) {
            float l = 0.f;
            #pragma unroll
            for (int i = 0; i < DHz; i++) l += qv[h * 8 + i] * k0s[h * 8 + i];
            l0[h] = l * scale;
            den[h] = fnbg;
            #pragma unroll
            for (int i = 0; i < DHz; i++) o[h][i] = fnbg * v0s[h * 8 + i];
        }

        const float4* kb = (const float4*)(g_k + nb * Dz);
        const float4* vb = (const float4*)(g_v + nb * Dz);
        for (int j = 0; j < cnt; j++) {
            int sj = lst_s[j];
            const float4* kr = kb + sj * 8;
            const float4* vr = vb + sj * 8;
            #pragma unroll
            for (int h = 0; h < Hz; h++) {
                float4 a = __ldg(kr + h * 2), cc = __ldg(kr + h * 2 + 1);
                float l = qv[h*8+0]*a.x + qv[h*8+1]*a.y + qv[h*8+2]*a.z + qv[h*8+3]*a.w
                        + qv[h*8+4]*cc.x + qv[h*8+5]*cc.y + qv[h*8+6]*cc.z + qv[h*8+7]*cc.w;
                float w = __expf(l * scale - l0[h]);
                den[h] += w;
                float4 va = __ldg(vr + h * 2), vc = __ldg(vr + h * 2 + 1);
                o[h][0] += w * va.x; o[h][1] += w * va.y;
                o[h][2] += w * va.z; o[h][3] += w * va.w;
                o[h][4] += w * vc.x; o[h][5] += w * vc.y;
                o[h][6] += w * vc.z; o[h][7] += w * vc.w;
            }
        }

        if (active) {
            float4* dst = (float4*)(g_attn + ((long)(b * Sz + sq) * Nz + n) * Dz);
            #pragma unroll
            for (int h = 0; h < Hz; h++) {
                float inv = 1.0f / den[h];
                dst[h * 2]     = make_float4(o[h][0]*inv, o[h][1]*inv,
                                             o[h][2]*inv, o[h][3]*inv);
                dst[h * 2 + 1] = make_float4(o[h][4]*inv, o[h][5]*inv,
                                             o[h][6]*inv, o[h][7]*inv);
            }
        }
    }
}

// ---------------- kernel E: expert-grouped tail, weights in registers --------
// grid = (b,e)*8 tiles; block 128 (4 warps); lane = dim; warp = 4 channels;
// each lane holds its COLUMNS of Wo/W1/W2 in registers (loaded once per block,
// amortized over ~cnt/8 tokens); activations broadcast via vectorized LDS.
__global__ __launch_bounds__(128, 2) void tail_kernel(
        const float* __restrict__ sW,  const float* __restrict__ sb,
        const float* __restrict__ Wo,  const float* __restrict__ ln2_g,
        const float* __restrict__ ln2_b,
        const float* __restrict__ W1,  const float* __restrict__ b1,
        const float* __restrict__ W2,  const float* __restrict__ b2,
        float* __restrict__ out) {
    int blk = blockIdx.x;
    int pe = blk >> 3, tile = blk & 7;
    int b = pe / Ez, e = pe % Ez;
    int cnt = g_counts[pe];
    if (cnt == 0) return;

    int t = threadIdx.x, warp = t >> 5, lane = t & 31;

    __shared__ float att_s[4][4][Dz];    // [warp][ch][dim] 2KB
    __shared__ float z2_s[4][4][Dz];     // 2KB
    __shared__ float f_s[4][4][DFFz];    // 4KB

    // per-lane weight columns (160 registers)
    float wo[Dz], w1a[Dz], w1b[Dz], w2[DFFz];
    #pragma unroll
    for (int i = 0; i < Dz; i++) {
        wo[i]  = __ldg(&Wo[e * Dz * Dz + i * Dz + lane]);
        w1a[i] = __ldg(&W1[e * Dz * DFFz + i * DFFz + lane]);
        w1b[i] = __ldg(&W1[e * Dz * DFFz + i * DFFz + 32 + lane]);
    }
    #pragma unroll
    for (int j = 0; j < DFFz; j++)
        w2[j] = __ldg(&W2[e * DFFz * Dz + j * Dz + lane]);

    const float sWl  = __ldg(&sW[lane]);
    const float sbl  = __ldg(&sb[lane]);
    const float g2l  = __ldg(&ln2_g[e * Dz + lane]);
    const float bl2l = __ldg(&ln2_b[e * Dz + lane]);
    const float b2l  = __ldg(&b2[e * Dz + lane]);
    const float b1a  = __ldg(&b1[e * DFFz + lane]);
    const float b1b  = __ldg(&b1[e * DFFz + 32 + lane]);

    const int* lst = &g_lists[pe * Sz];
    int n0 = warp * 4;

    for (int ti = tile; ti < cnt; ti += 8) {
        int s = lst[ti];
        long tok = (long)(b * Sz + s);

        // stage attention rows for this warp's 4 channels
        #pragma unroll
        for (int ch = 0; ch < 4; ch++)
            att_s[warp][ch][lane] =
                __ldg(&g_attn[(tok * Nz + n0 + ch) * Dz + lane]);
        __syncwarp();

        float h1c[4], z2c[4];
        #pragma unroll
        for (int ch = 0; ch < 4; ch++) {
            float xv = __ldg(&g_xns[tok * Nz + n0 + ch]);
            float h1 = xv * sWl + sbl;
            const float4* ap = (const float4*)att_s[warp][ch];
            #pragma unroll
            for (int j4 = 0; j4 < 8; j4++) {
                float4 a = ap[j4];
                h1 += a.x * wo[j4 * 4 + 0] + a.y * wo[j4 * 4 + 1]
                    + a.z * wo[j4 * 4 + 2] + a.w * wo[j4 * 4 + 3];
            }
            // LN2 across lanes
            float mu = h1;
            #pragma unroll
            for (int off = 16; off > 0; off >>= 1)
                mu += __shfl_xor_sync(FULLM, mu, off);
            mu *= (1.0f / Dz);
            float df = h1 - mu;
            float var = df * df;
            #pragma unroll
            for (int off = 16; off > 0; off >>= 1)
                var += __shfl_xor_sync(FULLM, var, off);
            var *= (1.0f / Dz);
            float z = df * rsqrtf(var + 1e-5f) * g2l + bl2l;
            z2_s[warp][ch][lane] = z;
            h1c[ch] = h1 + b2l;
            z2c[ch] = z;
        }
        __syncwarp();

        // FFN layer 1: f = relu(z2 @ W1 + b1)
        #pragma unroll
        for (int ch = 0; ch < 4; ch++) {
            float f0 = b1a, f1 = b1b;
            const float4* zp = (const float4*)z2_s[warp][ch];
            #pragma unroll
            for (int i4 = 0; i4 < 8; i4++) {
                float4 z = zp[i4];
                f0 += z.x * w1a[i4*4+0] + z.y * w1a[i4*4+1]
                    + z.z * w1a[i4*4+2] + z.w * w1a[i4*4+3];
                f1 += z.x * w1b[i4*4+0] + z.y * w1b[i4*4+1]
                    + z.z * w1b[i4*4+2] + z.w * w1b[i4*4+3];
            }
            f_s[warp][ch][lane]      = fmaxf(f0, 0.f);
            f_s[warp][ch][32 + lane] = fmaxf(f1, 0.f);
        }
        __syncwarp();

        // FFN layer 2: out = h1 + f @ W2 + b2
        #pragma unroll
        for (int ch = 0; ch < 4; ch++) {
            float acc = h1c[ch];
            const float4* fp = (const float4*)f_s[warp][ch];
            #pragma unroll
            for (int j4 = 0; j4 < 16; j4++) {
                float4 f = fp[j4];
                acc += f.x * w2[j4*4+0] + f.y * w2[j4*4+1]
                     + f.z * w2[j4*4+2] + f.w * w2[j4*4+3];
            }
            out[(tok * Nz + n0 + ch) * Dz + lane] = acc;
        }
        __syncwarp();
        (void)z2c;
    }
}

// ---------------- launch ------------------------------------------------------
extern "C" void kernel_launch(void* const* d_in, const int* in_sizes, int n_in,
                              void* d_out, int out_size) {
    const float* x        = (const float*)d_in[0];
    const float* ox       = (const float*)d_in[1];
    const float* start_W  = (const float*)d_in[2];
    const float* start_b  = (const float*)d_in[3];
    const float* Wq       = (const float*)d_in[4];
    const float* Wk       = (const float*)d_in[5];
    const float* Wv       = (const float*)d_in[6];
    const float* Wo       = (const float*)d_in[7];
    const float* ln1_g    = (const float*)d_in[8];
    const float* ln1_b    = (const float*)d_in[9];
    const float* ln2_g    = (const float*)d_in[10];
    const float* ln2_b    = (const float*)d_in[11];
    const float* W1       = (const float*)d_in[12];
    const float* b1       = (const float*)d_in[13];
    const float* W2       = (const float*)d_in[14];
    const float* b2       = (const float*)d_in[15];
    float* out = (float*)d_out;

    preprocess_kernel<<<Bz * Nz, 256>>>(x);
    assign_kernel<<<1, 256>>>(ox, start_b, ln1_g, ln1_b, Wk, Wv);
    qkv_kernel<<<Bz * Ez * 8, 128>>>(start_W, start_b, Wq, Wk, Wv, ln1_g, ln1_b);
    attn_kernel<<<Bz * Ez * 8, 128>>>();
    tail_kernel<<<Bz * Ez * 8, 128>>>(start_W, start_b, Wo, ln2_g, ln2_b,
                                      W1, b1, W2, b2, out);
}